// round 3
// baseline (speedup 1.0000x reference)
#include <cuda_runtime.h>

// ---------------------------------------------------------------------------
// MLPPredictor: score[e] = W3 @ relu(W2 @ relu(W1 @ [x[src];x[dst]] + b1) + b2) + b3
//
// Key restructuring: W1 @ concat(xs, xd) = W1a @ xs + W1b @ xd
//   -> precompute node-level PQ = X @ [W1a | W1b]^T  (50k x 512)
//   -> per-edge: H1 = relu(PQ[src][0:256] + PQ[dst][256:512] + b1), then
//      fused layer2 GEMM + layer3 dot, all in one CTA, H2 never hits gmem.
// All GEMMs use mma.sync m16n8k8 TF32 (fp32 accum) for rel_err ~3e-4 << 1e-3.
// ---------------------------------------------------------------------------

#define D        256
#define NMAX     50000
#define KT       32          // K tile for double-buffered weight streaming
#define LDT      36          // smem row stride (padded, stride%32==4 -> conflict free)
#define NKT      (D / KT)    // 8 K-tiles
#define LDH      260         // H1 smem row stride (256 + 4 pad)

// scratch: node-level partial products (cols 0..255 = P (src half), 256..511 = Q (dst half))
static __device__ float g_PQ[(long long)NMAX * 512];
static __device__ int   g_is64;

__device__ __forceinline__ unsigned f2tf(float f) {
    unsigned u;
    asm("cvt.rna.tf32.f32 %0, %1;" : "=r"(u) : "f"(f));
    return u;
}

__device__ __forceinline__ void mma8(float* d, const unsigned* a, const unsigned* b) {
    asm volatile(
        "mma.sync.aligned.m16n8k8.row.col.f32.tf32.tf32.f32 "
        "{%0,%1,%2,%3},{%4,%5,%6,%7},{%8,%9},{%0,%1,%2,%3};\n"
        : "+f"(d[0]), "+f"(d[1]), "+f"(d[2]), "+f"(d[3])
        : "r"(a[0]), "r"(a[1]), "r"(a[2]), "r"(a[3]), "r"(b[0]), "r"(b[1]));
}

// ---------------------------------------------------------------------------
// Kernel 1: g_PQ[i, j] = sum_k x[i,k] * W1[j & 255, (j<256 ? 0 : 256) + k]
// Grid: (ceil(n/128), 4). CTA tile 128x128, 8 warps, warp tile 64x32, K=256.
// ---------------------------------------------------------------------------
__global__ __launch_bounds__(256) void node_gemm(const float* __restrict__ x,
                                                 const float* __restrict__ W1,
                                                 int n_nodes) {
    extern __shared__ unsigned sm[];
    unsigned* As = sm;                  // [2][128][LDT]
    unsigned* Ws = sm + 2 * 128 * LDT;  // [2][128][LDT]

    const int tid  = threadIdx.x;
    const int lane = tid & 31, warp = tid >> 5;
    const int wm = warp >> 2, wn = warp & 3;
    const int g = lane >> 2, tg = lane & 3;
    const int m0 = blockIdx.x * 128;
    const int n0 = blockIdx.y * 128;         // 0..511
    const int wq  = (n0 >= 256) ? 256 : 0;   // weight column offset (src/dst half)
    const int wr0 = n0 & 255;                // weight row base

    float acc[4][4][4];
#pragma unroll
    for (int a = 0; a < 4; a++)
#pragma unroll
        for (int b = 0; b < 4; b++)
#pragma unroll
            for (int c = 0; c < 4; c++) acc[a][b][c] = 0.f;

    float4 ra[4], rw[4];
    int rowA[4], c4A[4];
#pragma unroll
    for (int i = 0; i < 4; i++) {
        int idx = tid + i * 256;   // 1024 float4 per 128x32 tile
        rowA[i] = idx >> 3;
        c4A[i]  = idx & 7;
    }

    auto LD = [&](int kt) {
#pragma unroll
        for (int i = 0; i < 4; i++) {
            int gr = m0 + rowA[i];
            if (gr >= n_nodes) gr = n_nodes - 1;
            ra[i] = *(const float4*)(x + (long long)gr * D + kt * KT + c4A[i] * 4);
            rw[i] = *(const float4*)(W1 + (long long)(wr0 + rowA[i]) * 512 + wq + kt * KT + c4A[i] * 4);
        }
    };
    auto ST = [&](int buf) {
#pragma unroll
        for (int i = 0; i < 4; i++) {
            unsigned* pa = As + buf * 128 * LDT + rowA[i] * LDT + c4A[i] * 4;
            pa[0] = f2tf(ra[i].x); pa[1] = f2tf(ra[i].y); pa[2] = f2tf(ra[i].z); pa[3] = f2tf(ra[i].w);
            unsigned* pw = Ws + buf * 128 * LDT + rowA[i] * LDT + c4A[i] * 4;
            pw[0] = f2tf(rw[i].x); pw[1] = f2tf(rw[i].y); pw[2] = f2tf(rw[i].z); pw[3] = f2tf(rw[i].w);
        }
    };

    LD(0); ST(0);
    __syncthreads();

    for (int kt = 0; kt < NKT; ++kt) {
        const int cur = kt & 1;
        if (kt + 1 < NKT) LD(kt + 1);
        const unsigned* Ab = As + cur * 128 * LDT;
        const unsigned* Wb = Ws + cur * 128 * LDT;
#pragma unroll
        for (int kk = 0; kk < KT / 8; ++kk) {
            unsigned af[4][4], bf[4][2];
#pragma unroll
            for (int mi = 0; mi < 4; ++mi) {
                int r = wm * 64 + mi * 16 + g;
                int c = kk * 8 + tg;
                af[mi][0] = Ab[r * LDT + c];
                af[mi][1] = Ab[(r + 8) * LDT + c];
                af[mi][2] = Ab[r * LDT + c + 4];
                af[mi][3] = Ab[(r + 8) * LDT + c + 4];
            }
#pragma unroll
            for (int ni = 0; ni < 4; ++ni) {
                int n = wn * 32 + ni * 8 + g;
                bf[ni][0] = Wb[n * LDT + kk * 8 + tg];
                bf[ni][1] = Wb[n * LDT + kk * 8 + tg + 4];
            }
#pragma unroll
            for (int mi = 0; mi < 4; ++mi)
#pragma unroll
                for (int ni = 0; ni < 4; ++ni) mma8(acc[mi][ni], af[mi], bf[ni]);
        }
        if (kt + 1 < NKT) ST(cur ^ 1);
        __syncthreads();
    }

#pragma unroll
    for (int mi = 0; mi < 4; ++mi) {
        int gr0 = m0 + wm * 64 + mi * 16 + g;
        int gr1 = gr0 + 8;
#pragma unroll
        for (int ni = 0; ni < 4; ++ni) {
            int gc = n0 + wn * 32 + ni * 8 + tg * 2;
            if (gr0 < n_nodes)
                *(float2*)(g_PQ + (long long)gr0 * 512 + gc) = make_float2(acc[mi][ni][0], acc[mi][ni][1]);
            if (gr1 < n_nodes)
                *(float2*)(g_PQ + (long long)gr1 * 512 + gc) = make_float2(acc[mi][ni][2], acc[mi][ni][3]);
        }
    }
}

// ---------------------------------------------------------------------------
// Kernel 2: detect whether src/dst are int64 or int32 (JAX x64 default is off,
// so jnp.int64 request usually becomes int32 — handle both).
// int64 with values < 50000 -> all high 32-bit words are 0.
// ---------------------------------------------------------------------------
__global__ void detect_idx64(const int* __restrict__ p, int E) {
    __shared__ int ok;
    if (threadIdx.x == 0) ok = 1;
    __syncthreads();
    int n = E < 1024 ? E : 1024;
    int bad = 0;
    for (int i = threadIdx.x; i < n; i += blockDim.x)
        if (p[2 * i + 1] != 0) bad = 1;
    if (bad) atomicAnd(&ok, 0);
    __syncthreads();
    if (threadIdx.x == 0) g_is64 = ok;
}

// ---------------------------------------------------------------------------
// Kernel 3: per-CTA 128 edges. Gather H1 = relu(P[src]+Q[dst]+b1) to smem,
// then two N=128 passes of TF32 MMA vs W2, fused relu(+b2)*w3 reduction.
// ---------------------------------------------------------------------------
__global__ __launch_bounds__(256) void edge_mlp(const void* __restrict__ srcv,
                                                const void* __restrict__ dstv,
                                                const float* __restrict__ b1,
                                                const float* __restrict__ W2,
                                                const float* __restrict__ b2,
                                                const float* __restrict__ W3,
                                                const float* __restrict__ b3,
                                                float* __restrict__ out, int E) {
    extern __shared__ unsigned sm[];
    unsigned* Hs  = sm;                         // [128][LDH] tf32
    unsigned* Ws2 = sm + 128 * LDH;             // [2][128][LDT] tf32
    float* b2s   = (float*)(Ws2 + 2 * 128 * LDT);  // 256
    float* w3s   = b2s + 256;                      // 256
    float* b1s   = w3s + 256;                      // 256
    float* score = b1s + 256;                      // 128

    const int tid  = threadIdx.x;
    const int lane = tid & 31, warp = tid >> 5;
    const int wm = warp >> 2, wn = warp & 3;
    const int g = lane >> 2, tg = lane & 3;
    const int e0 = blockIdx.x * 128;
    const int is64 = g_is64;

    b2s[tid < 256 ? tid : 0] = b2[tid < 256 ? tid : 0];
    w3s[tid] = W3[tid];
    b1s[tid] = b1[tid];
    if (tid < 128) score[tid] = b3[0];
    __syncthreads();

    // ---- gather + layer 1 (coalesced: 8 lanes span 128B of a row) ----
    {
        const int l8 = tid & 7;
        for (int r = tid >> 3; r < 128; r += 32) {
            int e = e0 + r;
            if (e >= E) e = 0;  // garbage rows: valid data, results never stored
            long long s, d;
            if (is64) {
                s = ((const long long*)srcv)[e];
                d = ((const long long*)dstv)[e];
            } else {
                s = ((const int*)srcv)[e];
                d = ((const int*)dstv)[e];
            }
            const float* Pr = g_PQ + s * 512;
            const float* Qr = g_PQ + d * 512 + 256;
#pragma unroll
            for (int c4 = l8; c4 < 64; c4 += 8) {
                float4 p  = *(const float4*)(Pr + c4 * 4);
                float4 q  = *(const float4*)(Qr + c4 * 4);
                float4 bb = *(const float4*)(b1s + c4 * 4);
                unsigned* hp = Hs + r * LDH + c4 * 4;
                hp[0] = f2tf(fmaxf(p.x + q.x + bb.x, 0.f));
                hp[1] = f2tf(fmaxf(p.y + q.y + bb.y, 0.f));
                hp[2] = f2tf(fmaxf(p.z + q.z + bb.z, 0.f));
                hp[3] = f2tf(fmaxf(p.w + q.w + bb.w, 0.f));
            }
        }
    }
    __syncthreads();

    float4 rw[4];
    int rowA[4], c4A[4];
#pragma unroll
    for (int i = 0; i < 4; i++) {
        int idx = tid + i * 256;
        rowA[i] = idx >> 3;
        c4A[i]  = idx & 7;
    }

    for (int nc = 0; nc < 2; ++nc) {
        const int n0 = nc * 128;
        float acc[4][4][4];
#pragma unroll
        for (int a = 0; a < 4; a++)
#pragma unroll
            for (int b = 0; b < 4; b++)
#pragma unroll
                for (int c = 0; c < 4; c++) acc[a][b][c] = 0.f;

        auto LDW = [&](int kt) {
#pragma unroll
            for (int i = 0; i < 4; i++)
                rw[i] = *(const float4*)(W2 + (long long)(n0 + rowA[i]) * 256 + kt * KT + c4A[i] * 4);
        };
        auto STW = [&](int buf) {
#pragma unroll
            for (int i = 0; i < 4; i++) {
                unsigned* pw = Ws2 + buf * 128 * LDT + rowA[i] * LDT + c4A[i] * 4;
                pw[0] = f2tf(rw[i].x); pw[1] = f2tf(rw[i].y); pw[2] = f2tf(rw[i].z); pw[3] = f2tf(rw[i].w);
            }
        };

        LDW(0); STW(0);
        __syncthreads();

        for (int kt = 0; kt < NKT; ++kt) {
            const int cur = kt & 1;
            if (kt + 1 < NKT) LDW(kt + 1);
            const unsigned* Wb = Ws2 + cur * 128 * LDT;
#pragma unroll
            for (int kk = 0; kk < KT / 8; ++kk) {
                unsigned af[4][4], bf[4][2];
                const int kbase = kt * KT + kk * 8;
#pragma unroll
                for (int mi = 0; mi < 4; ++mi) {
                    int r = wm * 64 + mi * 16 + g;
                    af[mi][0] = Hs[r * LDH + kbase + tg];
                    af[mi][1] = Hs[(r + 8) * LDH + kbase + tg];
                    af[mi][2] = Hs[r * LDH + kbase + tg + 4];
                    af[mi][3] = Hs[(r + 8) * LDH + kbase + tg + 4];
                }
#pragma unroll
                for (int ni = 0; ni < 4; ++ni) {
                    int n = wn * 32 + ni * 8 + g;
                    bf[ni][0] = Wb[n * LDT + kk * 8 + tg];
                    bf[ni][1] = Wb[n * LDT + kk * 8 + tg + 4];
                }
#pragma unroll
                for (int mi = 0; mi < 4; ++mi)
#pragma unroll
                    for (int ni = 0; ni < 4; ++ni) mma8(acc[mi][ni], af[mi], bf[ni]);
            }
            if (kt + 1 < NKT) STW(cur ^ 1);
            __syncthreads();
        }

        // ---- fused layer-2 bias/relu + layer-3 dot reduction ----
#pragma unroll
        for (int mi = 0; mi < 4; ++mi) {
            float rs0 = 0.f, rs1 = 0.f;
#pragma unroll
            for (int ni = 0; ni < 4; ++ni) {
                int n = n0 + wn * 32 + ni * 8 + tg * 2;
                float w0 = w3s[n], w1 = w3s[n + 1];
                float bb0 = b2s[n], bb1 = b2s[n + 1];
                rs0 += fmaxf(acc[mi][ni][0] + bb0, 0.f) * w0 + fmaxf(acc[mi][ni][1] + bb1, 0.f) * w1;
                rs1 += fmaxf(acc[mi][ni][2] + bb0, 0.f) * w0 + fmaxf(acc[mi][ni][3] + bb1, 0.f) * w1;
            }
            rs0 += __shfl_xor_sync(0xffffffffu, rs0, 1);
            rs0 += __shfl_xor_sync(0xffffffffu, rs0, 2);
            rs1 += __shfl_xor_sync(0xffffffffu, rs1, 1);
            rs1 += __shfl_xor_sync(0xffffffffu, rs1, 2);
            if (tg == 0) {
                atomicAdd(&score[wm * 64 + mi * 16 + g], rs0);
                atomicAdd(&score[wm * 64 + mi * 16 + g + 8], rs1);
            }
        }
        __syncthreads();
    }

    if (tid < 128) {
        int e = e0 + tid;
        if (e < E) out[e] = score[tid];
    }
}

// ---------------------------------------------------------------------------
// Launch
// ---------------------------------------------------------------------------
extern "C" void kernel_launch(void* const* d_in, const int* in_sizes, int n_in,
                              void* d_out, int out_size) {
    const float* x  = (const float*)d_in[0];
    const void*  sv = d_in[1];
    const void*  dv = d_in[2];
    const float* W1 = (const float*)d_in[3];
    const float* b1 = (const float*)d_in[4];
    const float* W2 = (const float*)d_in[5];
    const float* b2 = (const float*)d_in[6];
    const float* W3 = (const float*)d_in[7];
    const float* b3 = (const float*)d_in[8];
    float* out = (float*)d_out;

    const int n_nodes = in_sizes[0] / D;
    const int E       = in_sizes[1];

    const int SM1 = 2 * 2 * 128 * LDT * 4;                                   // 73728 B
    const int SM2 = (128 * LDH + 2 * 128 * LDT + 3 * 256 + 128) * 4;         // 173568 B
    cudaFuncSetAttribute(node_gemm, cudaFuncAttributeMaxDynamicSharedMemorySize, SM1);
    cudaFuncSetAttribute(edge_mlp,  cudaFuncAttributeMaxDynamicSharedMemorySize, SM2);

    dim3 g1((n_nodes + 127) / 128, 4);
    node_gemm<<<g1, 256, SM1>>>(x, W1, n_nodes);

    detect_idx64<<<1, 256>>>((const int*)sv, E);

    int g2 = (E + 127) / 128;
    edge_mlp<<<g2, 256, SM2>>>(sv, dv, b1, W2, b2, W3, b3, out, E);
}

// round 4
// speedup vs baseline: 1.0534x; 1.0534x over previous
#include <cuda_runtime.h>

// ---------------------------------------------------------------------------
// MLPPredictor: score[e] = W3 @ relu(W2 @ relu(W1 @ [x[src];x[dst]] + b1) + b2) + b3
//
// Restructuring: W1 @ concat(xs,xd) = W1a@xs + W1b@xd -> node-level PQ GEMM,
// then per-edge gather + fused layer2 GEMM + layer3 dot.
//
// R3 changes: MMA-fragment-packed shared-memory layout (1 LDS.128 / A-frag,
// 1 LDS.64 / B-frag instead of 6 scalar LDS per MMA), 64x64 warp tiles,
// edge CTA computes full N=256 in one pass (W2 streamed once per CTA).
// ---------------------------------------------------------------------------

#define D     256
#define NMAX  50000
#define AW    132      // A fragment block: 128 words + 4 pad (bank rotation)
#define BW    66       // B fragment block: 64 words + 2 pad

// Edge kernel smem: Afrag [8 Mi][32 Kk] blocks, Bfrag [2 buf][32 Ni][4 kk]
#define EA_WORDS (8 * 32 * AW)   // 33792
#define EB_WORDS (32 * 4 * BW)   // 8448
// Node kernel smem: Afrag [2][8 Mi][4 kk], Bfrag [2][32 Ni][4 kk]
#define NA_WORDS (8 * 4 * AW)    // 4224
#define NB_WORDS (32 * 4 * BW)   // 8448

static __device__ float g_PQ[(long long)NMAX * 512];
static __device__ int   g_is64;

__device__ __forceinline__ unsigned f2tf(float f) {
    unsigned u;
    asm("cvt.rna.tf32.f32 %0, %1;" : "=r"(u) : "f"(f));
    return u;
}

__device__ __forceinline__ void mma8(float* d, const unsigned* a, const unsigned* b) {
    asm volatile(
        "mma.sync.aligned.m16n8k8.row.col.f32.tf32.tf32.f32 "
        "{%0,%1,%2,%3},{%4,%5,%6,%7},{%8,%9},{%0,%1,%2,%3};\n"
        : "+f"(d[0]), "+f"(d[1]), "+f"(d[2]), "+f"(d[3])
        : "r"(a[0]), "r"(a[1]), "r"(a[2]), "r"(a[3]), "r"(b[0]), "r"(b[1]));
}

// ---------------------------------------------------------------------------
// Kernel 1: g_PQ[i, n0+n] = sum_k x[i,k] * W1[n, n0+k]   (n0 in {0,256})
// CTA tile 128x256, warp tile 64x64 (8 warps, 2x4), K streamed in tiles of 32.
// ---------------------------------------------------------------------------
__global__ __launch_bounds__(256) void node_gemm(const float* __restrict__ x,
                                                 const float* __restrict__ W1,
                                                 int n_nodes) {
    extern __shared__ unsigned sm[];
    unsigned* Af = sm;                   // [2][NA_WORDS]
    unsigned* Bf = sm + 2 * NA_WORDS;    // [2][NB_WORDS]

    const int tid  = threadIdx.x;
    const int lane = tid & 31, warp = tid >> 5;
    const int wm = warp >> 2, wn = warp & 3;
    const int g = lane >> 2, tg = lane & 3;
    const int m0 = blockIdx.x * 128;
    const int n0 = blockIdx.y * 256;

    float4 rav[4], rwv[8];

    // A loader: warp owns rows m0 + warp*16 + g {+0,+8}; 8-k octet at tg*8.
    auto LDA = [&](int kt) {
        int r0 = m0 + warp * 16 + g;
        int r1 = r0 + 8;
        if (r0 >= n_nodes) r0 = n_nodes - 1;
        if (r1 >= n_nodes) r1 = n_nodes - 1;
        const float* p0 = x + (long long)r0 * D + kt * 32 + tg * 8;
        const float* p1 = x + (long long)r1 * D + kt * 32 + tg * 8;
        rav[0] = *(const float4*)p0; rav[1] = *(const float4*)(p0 + 4);
        rav[2] = *(const float4*)p1; rav[3] = *(const float4*)(p1 + 4);
    };
    auto STA = [&](int buf) {
        unsigned* A = Af + buf * NA_WORDS;
        unsigned* ap = A + (warp * 4 + tg) * AW + g * 16;  // block (Mi=warp, kk=tg)
        const float* a0 = (const float*)&rav[0];
        const float* a1 = (const float*)&rav[1];
        const float* a2 = (const float*)&rav[2];
        const float* a3 = (const float*)&rav[3];
#pragma unroll
        for (int t = 0; t < 4; t++) {
            uint4 v;
            v.x = f2tf(a0[t]);  // (r0, c=t)
            v.y = f2tf(a2[t]);  // (r1, c=t)
            v.z = f2tf(a1[t]);  // (r0, c=t+4)
            v.w = f2tf(a3[t]);  // (r1, c=t+4)
            *(uint4*)(ap + t * 4) = v;
        }
    };
    // W loader: warp owns rows warp*32+p*8+g, octet at tg*8.
    auto LDW = [&](int kt) {
#pragma unroll
        for (int p = 0; p < 4; p++) {
            const float* base = W1 + (long long)(warp * 32 + p * 8 + g) * 512 + n0 + kt * 32 + tg * 8;
            rwv[2 * p]     = *(const float4*)base;
            rwv[2 * p + 1] = *(const float4*)(base + 4);
        }
    };
    auto STW = [&](int buf) {
        unsigned* B = Bf + buf * NB_WORDS;
#pragma unroll
        for (int p = 0; p < 4; p++) {
            unsigned* bp = B + ((warp * 4 + p) * 4 + tg) * BW + g * 8;  // (Ni, kk=tg)
            const float* lo = (const float*)&rwv[2 * p];
            const float* hi = (const float*)&rwv[2 * p + 1];
#pragma unroll
            for (int t = 0; t < 4; t++) {
                uint2 v; v.x = f2tf(lo[t]); v.y = f2tf(hi[t]);
                *(uint2*)(bp + t * 2) = v;
            }
        }
    };

    float acc[4][8][4];
#pragma unroll
    for (int a = 0; a < 4; a++)
#pragma unroll
        for (int b = 0; b < 8; b++)
#pragma unroll
            for (int c = 0; c < 4; c++) acc[a][b][c] = 0.f;

    LDA(0); LDW(0);
    STA(0); STW(0);
    __syncthreads();

    for (int kt = 0; kt < 8; ++kt) {
        const int cur = kt & 1;
        if (kt < 7) { LDA(kt + 1); LDW(kt + 1); }
        const unsigned* Ac = Af + cur * NA_WORDS;
        const unsigned* Bc = Bf + cur * NB_WORDS;
#pragma unroll
        for (int kk = 0; kk < 4; ++kk) {
            uint4 af[4]; uint2 bf[8];
#pragma unroll
            for (int mi = 0; mi < 4; ++mi)
                af[mi] = *(const uint4*)(Ac + ((wm * 4 + mi) * 4 + kk) * AW + lane * 4);
#pragma unroll
            for (int ni = 0; ni < 8; ++ni)
                bf[ni] = *(const uint2*)(Bc + ((wn * 8 + ni) * 4 + kk) * BW + lane * 2);
#pragma unroll
            for (int mi = 0; mi < 4; ++mi)
#pragma unroll
                for (int ni = 0; ni < 8; ++ni)
                    mma8(acc[mi][ni], (const unsigned*)&af[mi], (const unsigned*)&bf[ni]);
        }
        if (kt < 7) { STA(cur ^ 1); STW(cur ^ 1); }
        __syncthreads();
    }

#pragma unroll
    for (int mi = 0; mi < 4; ++mi) {
        int r0 = m0 + wm * 64 + mi * 16 + g;
        int r1 = r0 + 8;
#pragma unroll
        for (int ni = 0; ni < 8; ++ni) {
            int c = n0 + wn * 64 + ni * 8 + tg * 2;
            if (r0 < n_nodes)
                *(float2*)(g_PQ + (long long)r0 * 512 + c) = make_float2(acc[mi][ni][0], acc[mi][ni][1]);
            if (r1 < n_nodes)
                *(float2*)(g_PQ + (long long)r1 * 512 + c) = make_float2(acc[mi][ni][2], acc[mi][ni][3]);
        }
    }
}

// ---------------------------------------------------------------------------
// Kernel 2: detect int64 vs int32 index dtype (JAX x64-off downgrades int64).
// ---------------------------------------------------------------------------
__global__ void detect_idx64(const int* __restrict__ p, int E) {
    __shared__ int ok;
    if (threadIdx.x == 0) ok = 1;
    __syncthreads();
    int n = E < 1024 ? E : 1024;
    int bad = 0;
    for (int i = threadIdx.x; i < n; i += blockDim.x)
        if (p[2 * i + 1] != 0) bad = 1;
    if (bad) atomicAnd(&ok, 0);
    __syncthreads();
    if (threadIdx.x == 0) g_is64 = ok;
}

// ---------------------------------------------------------------------------
// Kernel 3: 128 edges per CTA. Gather H1 = relu(P[src]+Q[dst]+b1) directly
// into fragment layout; one N=256 MMA pass (warp 64x64); fused relu+dot.
// ---------------------------------------------------------------------------
__global__ __launch_bounds__(256) void edge_mlp(const void* __restrict__ srcv,
                                                const void* __restrict__ dstv,
                                                const float* __restrict__ b1,
                                                const float* __restrict__ W2,
                                                const float* __restrict__ b2,
                                                const float* __restrict__ W3,
                                                const float* __restrict__ b3,
                                                float* __restrict__ out, int E) {
    extern __shared__ unsigned sm[];
    unsigned* Af = sm;                       // [EA_WORDS]
    unsigned* Bf = sm + EA_WORDS;            // [2][EB_WORDS]
    float* b2s   = (float*)(Bf + 2 * EB_WORDS);   // 256
    float* w3s   = b2s + 256;                     // 256
    float* b1s   = w3s + 256;                     // 256
    float* score = b1s + 256;                     // 128

    const int tid  = threadIdx.x;
    const int lane = tid & 31, warp = tid >> 5;
    const int wm = warp >> 2, wn = warp & 3;
    const int g = lane >> 2, tg = lane & 3;
    const int e0 = blockIdx.x * 128;
    const int is64 = g_is64;

    b2s[tid] = b2[tid];
    w3s[tid] = W3[tid];
    b1s[tid] = b1[tid];
    if (tid < 128) score[tid] = b3[0];
    __syncthreads();

    float4 rwv[8];
    auto LDW = [&](int kt) {
#pragma unroll
        for (int p = 0; p < 4; p++) {
            const float* base = W2 + (long long)(warp * 32 + p * 8 + g) * 256 + kt * 32 + tg * 8;
            rwv[2 * p]     = *(const float4*)base;
            rwv[2 * p + 1] = *(const float4*)(base + 4);
        }
    };
    auto STW = [&](int buf) {
        unsigned* B = Bf + buf * EB_WORDS;
#pragma unroll
        for (int p = 0; p < 4; p++) {
            unsigned* bp = B + ((warp * 4 + p) * 4 + tg) * BW + g * 8;
            const float* lo = (const float*)&rwv[2 * p];
            const float* hi = (const float*)&rwv[2 * p + 1];
#pragma unroll
            for (int t = 0; t < 4; t++) {
                uint2 v; v.x = f2tf(lo[t]); v.y = f2tf(hi[t]);
                *(uint2*)(bp + t * 2) = v;
            }
        }
    };

    LDW(0);  // overlap W2 tile-0 loads with gather

    // ---- gather + layer 1, written directly in fragment layout ----
    {
        const int l8 = tid & 7;
#pragma unroll
        for (int rr = 0; rr < 4; rr++) {
            int r = (tid >> 3) + rr * 32;
            int e = e0 + r;
            if (e >= E) e = 0;  // garbage rows computed, never stored
            long long s, d;
            if (is64) {
                s = ((const long long*)srcv)[e];
                d = ((const long long*)dstv)[e];
            } else {
                s = ((const int*)srcv)[e];
                d = ((const int*)dstv)[e];
            }
            const float* Pr = g_PQ + s * 512;
            const float* Qr = g_PQ + d * 512 + 256;
            const int Mi = r >> 4, gg = r & 7, hl = (r >> 3) & 1;
#pragma unroll
            for (int i = 0; i < 8; i++) {
                int c4 = l8 + i * 8;   // 0..63
                float4 p  = *(const float4*)(Pr + c4 * 4);
                float4 q  = *(const float4*)(Qr + c4 * 4);
                float4 bb = *(const float4*)(b1s + c4 * 4);
                int Kk = c4 >> 1, ch = c4 & 1;
                unsigned* hp = Af + (Mi * 32 + Kk) * AW + gg * 16 + hl + 2 * ch;
                hp[0]  = f2tf(fmaxf(p.x + q.x + bb.x, 0.f));
                hp[4]  = f2tf(fmaxf(p.y + q.y + bb.y, 0.f));
                hp[8]  = f2tf(fmaxf(p.z + q.z + bb.z, 0.f));
                hp[12] = f2tf(fmaxf(p.w + q.w + bb.w, 0.f));
            }
        }
    }
    STW(0);
    __syncthreads();

    float acc[4][8][4];
#pragma unroll
    for (int a = 0; a < 4; a++)
#pragma unroll
        for (int b = 0; b < 8; b++)
#pragma unroll
            for (int c = 0; c < 4; c++) acc[a][b][c] = 0.f;

    for (int kt = 0; kt < 8; ++kt) {
        const int cur = kt & 1;
        if (kt < 7) LDW(kt + 1);
        const unsigned* Bc = Bf + cur * EB_WORDS;
#pragma unroll
        for (int kk = 0; kk < 4; ++kk) {
            const int Kkg = kt * 4 + kk;
            uint4 af[4]; uint2 bf[8];
#pragma unroll
            for (int mi = 0; mi < 4; ++mi)
                af[mi] = *(const uint4*)(Af + ((wm * 4 + mi) * 32 + Kkg) * AW + lane * 4);
#pragma unroll
            for (int ni = 0; ni < 8; ++ni)
                bf[ni] = *(const uint2*)(Bc + ((wn * 8 + ni) * 4 + kk) * BW + lane * 2);
#pragma unroll
            for (int mi = 0; mi < 4; ++mi)
#pragma unroll
                for (int ni = 0; ni < 8; ++ni)
                    mma8(acc[mi][ni], (const unsigned*)&af[mi], (const unsigned*)&bf[ni]);
        }
        if (kt < 7) STW(cur ^ 1);
        __syncthreads();
    }

    // ---- fused layer-2 bias/relu + layer-3 dot reduction ----
#pragma unroll
    for (int mi = 0; mi < 4; ++mi) {
        float rs0 = 0.f, rs1 = 0.f;
#pragma unroll
        for (int ni = 0; ni < 8; ++ni) {
            int n = wn * 64 + ni * 8 + tg * 2;
            float w0 = w3s[n], w1 = w3s[n + 1];
            float c0 = b2s[n], c1 = b2s[n + 1];
            rs0 += fmaxf(acc[mi][ni][0] + c0, 0.f) * w0 + fmaxf(acc[mi][ni][1] + c1, 0.f) * w1;
            rs1 += fmaxf(acc[mi][ni][2] + c0, 0.f) * w0 + fmaxf(acc[mi][ni][3] + c1, 0.f) * w1;
        }
        rs0 += __shfl_xor_sync(0xffffffffu, rs0, 1);
        rs0 += __shfl_xor_sync(0xffffffffu, rs0, 2);
        rs1 += __shfl_xor_sync(0xffffffffu, rs1, 1);
        rs1 += __shfl_xor_sync(0xffffffffu, rs1, 2);
        if (tg == 0) {
            atomicAdd(&score[wm * 64 + mi * 16 + g], rs0);
            atomicAdd(&score[wm * 64 + mi * 16 + g + 8], rs1);
        }
    }
    __syncthreads();

    if (tid < 128) {
        int e = e0 + tid;
        if (e < E) out[e] = score[tid];
    }
}

// ---------------------------------------------------------------------------
// Launch
// ---------------------------------------------------------------------------
extern "C" void kernel_launch(void* const* d_in, const int* in_sizes, int n_in,
                              void* d_out, int out_size) {
    const float* x  = (const float*)d_in[0];
    const void*  sv = d_in[1];
    const void*  dv = d_in[2];
    const float* W1 = (const float*)d_in[3];
    const float* b1 = (const float*)d_in[4];
    const float* W2 = (const float*)d_in[5];
    const float* b2 = (const float*)d_in[6];
    const float* W3 = (const float*)d_in[7];
    const float* b3 = (const float*)d_in[8];
    float* out = (float*)d_out;

    const int n_nodes = in_sizes[0] / D;
    const int E       = in_sizes[1];

    const int SM_NODE = (2 * NA_WORDS + 2 * NB_WORDS) * 4;            // 101376 B
    const int SM_EDGE = (EA_WORDS + 2 * EB_WORDS + 896) * 4;          // 206336 B
    cudaFuncSetAttribute(node_gemm, cudaFuncAttributeMaxDynamicSharedMemorySize, SM_NODE);
    cudaFuncSetAttribute(edge_mlp,  cudaFuncAttributeMaxDynamicSharedMemorySize, SM_EDGE);

    dim3 g1((n_nodes + 127) / 128, 2);
    node_gemm<<<g1, 256, SM_NODE>>>(x, W1, n_nodes);

    detect_idx64<<<1, 256>>>((const int*)sv, E);

    int g2 = (E + 127) / 128;
    edge_mlp<<<g2, 256, SM_EDGE>>>(sv, dv, b1, W2, b2, W3, b3, out, E);
}

// round 6
// speedup vs baseline: 1.3543x; 1.2856x over previous
#include <cuda_runtime.h>
#include <cuda_fp16.h>

// ---------------------------------------------------------------------------
// MLPPredictor: score[e] = W3 @ relu(W2 @ relu(W1 @ [x[src];x[dst]] + b1) + b2) + b3
//
// W1 @ concat(xs,xd) = W1a@xs + W1b@xd -> node-level PQ GEMM (fp32 out),
// then per-edge gather + fused layer2 GEMM + layer3 dot.
//
// R6: fp16 m16n8k16 mma.sync (2x tf32 rate, same 10-bit mantissa), weights
// pre-converted to fp16 once, fragment-packed smem (LDS.128/LDS.64 per frag).
// ---------------------------------------------------------------------------

#define D 256
#define NMAX 50000
#define AW 132                 // A block (16m x 16k = 128 words) + 4 pad
#define BW 66                  // B block (8n  x 16k =  64 words) + 2 pad
#define EA_WORDS (8 * 16 * AW) // edge A: 8 Mi x 16 Kk blocks = 16896
#define BCH_WORDS (32 * 2 * BW)// B chunk (32 k): 32 Ni x 2 Kk = 4224
#define NACH_WORDS (8 * 2 * AW)// node A chunk: 8 Mi x 2 Kk    = 2112

static __device__ float g_PQ[(long long)NMAX * 512];
static __device__ int   g_is64;
static __device__ __align__(16) __half g_W1h[256 * 512];
static __device__ __align__(16) __half g_W2h[256 * 256];

__device__ __forceinline__ unsigned f2h2(float lo, float hi) {
    __half2 h = __floats2half2_rn(lo, hi);
    return *reinterpret_cast<unsigned*>(&h);
}

__device__ __forceinline__ void mma16(float* d, const unsigned* a, const unsigned* b) {
    asm volatile(
        "mma.sync.aligned.m16n8k16.row.col.f32.f16.f16.f32 "
        "{%0,%1,%2,%3},{%4,%5,%6,%7},{%8,%9},{%0,%1,%2,%3};\n"
        : "+f"(d[0]), "+f"(d[1]), "+f"(d[2]), "+f"(d[3])
        : "r"(a[0]), "r"(a[1]), "r"(a[2]), "r"(a[3]), "r"(b[0]), "r"(b[1]));
}

// ---- B chunk load/store: thread = n-row, 32 halves (4 x uint4) per chunk ----
__device__ __forceinline__ void ldBh(const __half* Wrow, int kt, uint4* r4) {
    const uint4* p = (const uint4*)(Wrow + kt * 32);
#pragma unroll
    for (int i = 0; i < 4; i++) r4[i] = p[i];
}
__device__ __forceinline__ void stBh(unsigned* Bbuf, int tid, const uint4* r4) {
    const int Ni = tid >> 3, g = tid & 7;
#pragma unroll
    for (int i = 0; i < 4; i++) {
        // block (Ni, Kkloc=i>>1); halves j*2 -> tg=j, reg=i&1
        unsigned* q = Bbuf + (Ni * 2 + (i >> 1)) * BW + g * 8 + (i & 1);
        q[0] = r4[i].x; q[2] = r4[i].y; q[4] = r4[i].z; q[6] = r4[i].w;
    }
}

// ---------------------------------------------------------------------------
// Weight pre-conversion: fp32 -> fp16 (runs every call; deterministic).
// ---------------------------------------------------------------------------
__global__ void convert_weights(const float* __restrict__ W1, const float* __restrict__ W2) {
    int idx = blockIdx.x * blockDim.x + threadIdx.x;   // one float4 each
    if (idx < 32768) {
        float4 v = ((const float4*)W1)[idx];
        ((__half2*)g_W1h)[idx * 2]     = __floats2half2_rn(v.x, v.y);
        ((__half2*)g_W1h)[idx * 2 + 1] = __floats2half2_rn(v.z, v.w);
    } else if (idx < 49152) {
        int j = idx - 32768;
        float4 v = ((const float4*)W2)[j];
        ((__half2*)g_W2h)[j * 2]     = __floats2half2_rn(v.x, v.y);
        ((__half2*)g_W2h)[j * 2 + 1] = __floats2half2_rn(v.z, v.w);
    }
}

// ---------------------------------------------------------------------------
// Kernel 1: g_PQ[i, n0+c] = sum_k x[i,k] * W1[c, n0+k]
// CTA tile 128x256, warp tile 64x64 (8 warps, 2x4), K chunks of 32, dbl-buf.
// ---------------------------------------------------------------------------
__global__ __launch_bounds__(256) void node_gemm(const float* __restrict__ x,
                                                 int n_nodes) {
    extern __shared__ unsigned sm[];
    unsigned* Af = sm;                      // [2][NACH_WORDS]
    unsigned* Bf = sm + 2 * NACH_WORDS;     // [2][BCH_WORDS]

    const int tid = threadIdx.x, lane = tid & 31, warp = tid >> 5;
    const int wm = warp >> 2, wn = warp & 3;
    const int g = lane >> 2, tg = lane & 3;
    const int m0 = blockIdx.x * 128, n0 = blockIdx.y * 256;

    // A loader: thread t -> row rA = t&127, k-half hA = t>>7 (16 halves)
    const int rA = tid & 127, hA = tid >> 7;
    const int gA = (rA & 15) & 7, rsA = (rA & 15) >> 3;
    float4 rav[4]; uint4 rwv[4];

    auto LDA = [&](int kt) {
        int gr = m0 + rA; if (gr >= n_nodes) gr = n_nodes - 1;
        const float4* p = (const float4*)(x + (long long)gr * D + kt * 32 + hA * 16);
#pragma unroll
        for (int i = 0; i < 4; i++) rav[i] = p[i];
    };
    auto STA = [&](int buf) {
        unsigned* base = Af + buf * NACH_WORDS + ((rA >> 4) * 2 + hA) * AW + gA * 16 + rsA;
#pragma unroll
        for (int i = 0; i < 4; i++) {
            unsigned* q = base + (i & 1) * 8 + (i >> 1) * 2;
            q[0] = f2h2(rav[i].x, rav[i].y);
            q[4] = f2h2(rav[i].z, rav[i].w);
        }
    };
    const __half* Brow = g_W1h + (long long)tid * 512 + n0;
    auto LDW = [&](int kt) { ldBh(Brow, kt, rwv); };
    auto STW = [&](int buf) { stBh(Bf + buf * BCH_WORDS, tid, rwv); };

    float acc[4][8][4];
#pragma unroll
    for (int a = 0; a < 4; a++)
#pragma unroll
        for (int b = 0; b < 8; b++)
#pragma unroll
            for (int c = 0; c < 4; c++) acc[a][b][c] = 0.f;

    LDA(0); LDW(0); STA(0); STW(0);
    __syncthreads();

    for (int kt = 0; kt < 8; ++kt) {
        const int cur = kt & 1;
        if (kt < 7) { LDA(kt + 1); LDW(kt + 1); }
        const unsigned* Ac = Af + cur * NACH_WORDS;
        const unsigned* Bc = Bf + cur * BCH_WORDS;
#pragma unroll
        for (int h = 0; h < 2; ++h) {
            uint4 af[4]; uint2 bf[8];
#pragma unroll
            for (int mi = 0; mi < 4; ++mi)
                af[mi] = *(const uint4*)(Ac + ((wm * 4 + mi) * 2 + h) * AW + lane * 4);
#pragma unroll
            for (int ni = 0; ni < 8; ++ni)
                bf[ni] = *(const uint2*)(Bc + ((wn * 8 + ni) * 2 + h) * BW + lane * 2);
#pragma unroll
            for (int mi = 0; mi < 4; ++mi)
#pragma unroll
                for (int ni = 0; ni < 8; ++ni)
                    mma16(acc[mi][ni], (const unsigned*)&af[mi], (const unsigned*)&bf[ni]);
        }
        if (kt < 7) { STA(cur ^ 1); STW(cur ^ 1); }
        __syncthreads();
    }

#pragma unroll
    for (int mi = 0; mi < 4; ++mi) {
        int r0 = m0 + wm * 64 + mi * 16 + g;
        int r1 = r0 + 8;
#pragma unroll
        for (int ni = 0; ni < 8; ++ni) {
            int c = n0 + wn * 64 + ni * 8 + tg * 2;
            if (r0 < n_nodes)
                *(float2*)(g_PQ + (long long)r0 * 512 + c) = make_float2(acc[mi][ni][0], acc[mi][ni][1]);
            if (r1 < n_nodes)
                *(float2*)(g_PQ + (long long)r1 * 512 + c) = make_float2(acc[mi][ni][2], acc[mi][ni][3]);
        }
    }
}

// ---------------------------------------------------------------------------
// Kernel 2: index dtype detection (JAX x64-off downgrades int64 -> int32).
// ---------------------------------------------------------------------------
__global__ void detect_idx64(const int* __restrict__ p, int E) {
    __shared__ int ok;
    if (threadIdx.x == 0) ok = 1;
    __syncthreads();
    int n = E < 1024 ? E : 1024;
    int bad = 0;
    for (int i = threadIdx.x; i < n; i += blockDim.x)
        if (p[2 * i + 1] != 0) bad = 1;
    if (bad) atomicAnd(&ok, 0);
    __syncthreads();
    if (threadIdx.x == 0) g_is64 = ok;
}

// ---------------------------------------------------------------------------
// Kernel 3: 128 edges/CTA. Gather H1 = relu(P[src]+Q[dst]+b1) into fragment
// layout (fp16), one N=256 MMA pass (warp 64x64), fused relu(+b2)*w3 + b3.
// ---------------------------------------------------------------------------
__global__ __launch_bounds__(256) void edge_mlp(const void* __restrict__ srcv,
                                                const void* __restrict__ dstv,
                                                const float* __restrict__ b1,
                                                const float* __restrict__ b2,
                                                const float* __restrict__ W3,
                                                const float* __restrict__ b3,
                                                float* __restrict__ out, int E) {
    extern __shared__ unsigned sm[];
    unsigned* Af = sm;                        // [EA_WORDS]
    unsigned* Bf = sm + EA_WORDS;             // [2][BCH_WORDS]
    float* b2s   = (float*)(Bf + 2 * BCH_WORDS);  // 256
    float* w3s   = b2s + 256;                     // 256
    float* b1s   = w3s + 256;                     // 256
    float* score = b1s + 256;                     // 128

    const int tid = threadIdx.x, lane = tid & 31, warp = tid >> 5;
    const int wm = warp >> 2, wn = warp & 3;
    const int g = lane >> 2, tg = lane & 3;
    const int e0 = blockIdx.x * 128;
    const int is64 = g_is64;

    b2s[tid] = b2[tid];
    w3s[tid] = W3[tid];
    b1s[tid] = b1[tid];
    if (tid < 128) score[tid] = b3[0];
    __syncthreads();

    uint4 rwv[4];
    const __half* Brow = g_W2h + (long long)tid * 256;
    auto LDW = [&](int kt) { ldBh(Brow, kt, rwv); };
    auto STW = [&](int buf) { stBh(Bf + buf * BCH_WORDS, tid, rwv); };

    LDW(0);  // overlap W2 chunk-0 loads with the gather

    // ---- gather + layer 1, written directly in fp16 fragment layout ----
    {
        const int l8 = tid & 7;
#pragma unroll
        for (int rr = 0; rr < 4; rr++) {
            int r = (tid >> 3) + rr * 32;
            int e = e0 + r;
            if (e >= E) e = 0;   // garbage rows computed, never stored
            long long s, d;
            if (is64) { s = ((const long long*)srcv)[e]; d = ((const long long*)dstv)[e]; }
            else      { s = ((const int*)srcv)[e];       d = ((const int*)dstv)[e]; }
            const float* Pr = g_PQ + s * 512;
            const float* Qr = g_PQ + d * 512 + 256;
            const int Mi = r >> 4, gg = (r & 15) & 7, rs = (r & 15) >> 3;
#pragma unroll
            for (int i = 0; i < 8; i++) {
                int c4 = l8 + i * 8;      // float4 index, 0..63
                float4 p  = *(const float4*)(Pr + c4 * 4);
                float4 q  = *(const float4*)(Qr + c4 * 4);
                float4 bb = *(const float4*)(b1s + c4 * 4);
                float h0 = fmaxf(p.x + q.x + bb.x, 0.f);
                float h1 = fmaxf(p.y + q.y + bb.y, 0.f);
                float h2 = fmaxf(p.z + q.z + bb.z, 0.f);
                float h3 = fmaxf(p.w + q.w + bb.w, 0.f);
                const int Kk = c4 >> 2, ii = c4 & 3;
                unsigned* qp = Af + (Mi * 16 + Kk) * AW + gg * 16 + rs + (ii & 1) * 8 + (ii >> 1) * 2;
                qp[0] = f2h2(h0, h1);
                qp[4] = f2h2(h2, h3);
            }
        }
    }
    STW(0);
    __syncthreads();

    float acc[4][8][4];
#pragma unroll
    for (int a = 0; a < 4; a++)
#pragma unroll
        for (int b = 0; b < 8; b++)
#pragma unroll
            for (int c = 0; c < 4; c++) acc[a][b][c] = 0.f;

    for (int kt = 0; kt < 8; ++kt) {
        const int cur = kt & 1;
        if (kt < 7) LDW(kt + 1);
        const unsigned* Bc = Bf + cur * BCH_WORDS;
#pragma unroll
        for (int h = 0; h < 2; ++h) {
            const int Kkg = kt * 2 + h;
            uint4 af[4]; uint2 bf[8];
#pragma unroll
            for (int mi = 0; mi < 4; ++mi)
                af[mi] = *(const uint4*)(Af + ((wm * 4 + mi) * 16 + Kkg) * AW + lane * 4);
#pragma unroll
            for (int ni = 0; ni < 8; ++ni)
                bf[ni] = *(const uint2*)(Bc + ((wn * 8 + ni) * 2 + h) * BW + lane * 2);
#pragma unroll
            for (int mi = 0; mi < 4; ++mi)
#pragma unroll
                for (int ni = 0; ni < 8; ++ni)
                    mma16(acc[mi][ni], (const unsigned*)&af[mi], (const unsigned*)&bf[ni]);
        }
        if (kt < 7) STW(cur ^ 1);
        __syncthreads();
    }

    // ---- fused layer-2 bias/relu + layer-3 dot reduction ----
#pragma unroll
    for (int mi = 0; mi < 4; ++mi) {
        float rs0 = 0.f, rs1 = 0.f;
#pragma unroll
        for (int ni = 0; ni < 8; ++ni) {
            int n = wn * 64 + ni * 8 + tg * 2;
            float w0 = w3s[n], w1 = w3s[n + 1];
            float c0 = b2s[n], c1 = b2s[n + 1];
            rs0 += fmaxf(acc[mi][ni][0] + c0, 0.f) * w0 + fmaxf(acc[mi][ni][1] + c1, 0.f) * w1;
            rs1 += fmaxf(acc[mi][ni][2] + c0, 0.f) * w0 + fmaxf(acc[mi][ni][3] + c1, 0.f) * w1;
        }
        rs0 += __shfl_xor_sync(0xffffffffu, rs0, 1);
        rs0 += __shfl_xor_sync(0xffffffffu, rs0, 2);
        rs1 += __shfl_xor_sync(0xffffffffu, rs1, 1);
        rs1 += __shfl_xor_sync(0xffffffffu, rs1, 2);
        if (tg == 0) {
            atomicAdd(&score[wm * 64 + mi * 16 + g], rs0);
            atomicAdd(&score[wm * 64 + mi * 16 + g + 8], rs1);
        }
    }
    __syncthreads();

    if (tid < 128) {
        int e = e0 + tid;
        if (e < E) out[e] = score[tid];
    }
}

// ---------------------------------------------------------------------------
// Launch
// ---------------------------------------------------------------------------
extern "C" void kernel_launch(void* const* d_in, const int* in_sizes, int n_in,
                              void* d_out, int out_size) {
    const float* x  = (const float*)d_in[0];
    const void*  sv = d_in[1];
    const void*  dv = d_in[2];
    const float* W1 = (const float*)d_in[3];
    const float* b1 = (const float*)d_in[4];
    const float* W2 = (const float*)d_in[5];
    const float* b2 = (const float*)d_in[6];
    const float* W3 = (const float*)d_in[7];
    const float* b3 = (const float*)d_in[8];
    float* out = (float*)d_out;

    const int n_nodes = in_sizes[0] / D;
    const int E       = in_sizes[1];

    const int SM_NODE = (2 * NACH_WORDS + 2 * BCH_WORDS) * 4;   // 50688 B
    const int SM_EDGE = (EA_WORDS + 2 * BCH_WORDS + 896) * 4;   // 104960 B
    cudaFuncSetAttribute(node_gemm, cudaFuncAttributeMaxDynamicSharedMemorySize, SM_NODE);
    cudaFuncSetAttribute(edge_mlp,  cudaFuncAttributeMaxDynamicSharedMemorySize, SM_EDGE);

    convert_weights<<<192, 256>>>(W1, W2);

    dim3 g1((n_nodes + 127) / 128, 2);
    node_gemm<<<g1, 256, SM_NODE>>>(x, n_nodes);

    detect_idx64<<<1, 256>>>((const int*)sv, E);

    int g2 = (E + 127) / 128;
    edge_mlp<<<g2, 256, SM_EDGE>>>(sv, dv, b1, b2, W3, b3, out, E);
}

// round 9
// speedup vs baseline: 1.5056x; 1.1117x over previous
#include <cuda_runtime.h>
#include <cuda_fp16.h>

// ---------------------------------------------------------------------------
// MLPPredictor: score[e] = W3 @ relu(W2 @ relu(W1 @ [x[src];x[dst]] + b1) + b2) + b3
//
// W1 @ concat(xs,xd) = W1a@xs + W1b@xd -> node-level PQ GEMM (fp32 out),
// then per-edge gather + fused layer2 GEMM + layer3 dot.
//
// R7: 512 threads / 16 warps per CTA, warp tile 64x32 (full N=256 in one
// pass), acc 64 regs -> 4 warps/SMSP for latency cover. fp16 m16n8k16 MMA,
// fragment-packed smem, weights pre-converted to fp16.
// ---------------------------------------------------------------------------

#define D 256
#define NMAX 50000
#define AW 132                  // A block (16m x 16k = 128 words) + 4 pad
#define BW 66                   // B block (8n  x 16k =  64 words) + 2 pad
#define EA_WORDS (8 * 16 * AW)  // edge A: 8 Mi x 16 Kk blocks = 16896
#define BCH_WORDS (32 * 2 * BW) // B chunk (32 k): 32 Ni x 2 Kk = 4224
#define NACH_WORDS (8 * 2 * AW) // node A chunk: 8 Mi x 2 Kk    = 2112

static __device__ float g_PQ[(long long)NMAX * 512];
static __device__ int   g_is64;
static __device__ __align__(16) __half g_W1h[256 * 512];
static __device__ __align__(16) __half g_W2h[256 * 256];

__device__ __forceinline__ unsigned f2h2(float lo, float hi) {
    __half2 h = __floats2half2_rn(lo, hi);
    return *reinterpret_cast<unsigned*>(&h);
}

__device__ __forceinline__ void mma16(float* d, const unsigned* a, const unsigned* b) {
    asm volatile(
        "mma.sync.aligned.m16n8k16.row.col.f32.f16.f16.f32 "
        "{%0,%1,%2,%3},{%4,%5,%6,%7},{%8,%9},{%0,%1,%2,%3};\n"
        : "+f"(d[0]), "+f"(d[1]), "+f"(d[2]), "+f"(d[3])
        : "r"(a[0]), "r"(a[1]), "r"(a[2]), "r"(a[3]), "r"(b[0]), "r"(b[1]));
}

// ---- B chunk (256 rows x 32 halves) split across 512 threads ----
// thread: row = tid>>1 (0..255), hB = tid&1 (which 16-half group)
__device__ __forceinline__ void ldBh2(const __half* p, uint4* r2) {
    r2[0] = ((const uint4*)p)[0];
    r2[1] = ((const uint4*)p)[1];
}
__device__ __forceinline__ void stBh2(unsigned* Bbuf, int tid, const uint4* r2) {
    const int row = tid >> 1, hB = tid & 1;
    const int Ni = row >> 3, g = row & 7;
#pragma unroll
    for (int ii = 0; ii < 2; ii++) {
        int i = hB * 2 + ii;   // float4 index within the row's 32 halves
        unsigned* q = Bbuf + (Ni * 2 + (i >> 1)) * BW + g * 8 + (i & 1);
        q[0] = r2[ii].x; q[2] = r2[ii].y; q[4] = r2[ii].z; q[6] = r2[ii].w;
    }
}

// ---------------------------------------------------------------------------
// Weight pre-conversion: fp32 -> fp16 (deterministic, runs every call).
// ---------------------------------------------------------------------------
__global__ void convert_weights(const float* __restrict__ W1, const float* __restrict__ W2) {
    int idx = blockIdx.x * blockDim.x + threadIdx.x;   // one float4 each
    if (idx < 32768) {
        float4 v = ((const float4*)W1)[idx];
        ((__half2*)g_W1h)[idx * 2]     = __floats2half2_rn(v.x, v.y);
        ((__half2*)g_W1h)[idx * 2 + 1] = __floats2half2_rn(v.z, v.w);
    } else if (idx < 49152) {
        int j = idx - 32768;
        float4 v = ((const float4*)W2)[j];
        ((__half2*)g_W2h)[j * 2]     = __floats2half2_rn(v.x, v.y);
        ((__half2*)g_W2h)[j * 2 + 1] = __floats2half2_rn(v.z, v.w);
    }
}

// ---------------------------------------------------------------------------
// Kernel 1: g_PQ[i, n0+c] = sum_k x[i,k] * W1[c, n0+k]
// CTA 128x256, 16 warps, warp tile 64x32 (wm 2 x wn 8), K chunks of 32.
// ---------------------------------------------------------------------------
__global__ __launch_bounds__(512) void node_gemm(const float* __restrict__ x,
                                                 int n_nodes) {
    extern __shared__ unsigned sm[];
    unsigned* Af = sm;                      // [2][NACH_WORDS]
    unsigned* Bf = sm + 2 * NACH_WORDS;     // [2][BCH_WORDS]

    const int tid = threadIdx.x, lane = tid & 31, warp = tid >> 5;
    const int wm = warp >> 3, wn = warp & 7;
    const int g = lane >> 2, tg = lane & 3;
    const int m0 = blockIdx.x * 128, n0 = blockIdx.y * 256;

    // A loader: item = tid>>1 covers (row, k-half); sub = tid&1 picks 8 floats
    const int item = tid >> 1, sub = tid & 1;
    const int rA = item & 127, hA = item >> 7;
    const int gA = (rA & 15) & 7, rsA = (rA & 15) >> 3;
    float4 rav[2]; uint4 rwv[2];

    auto LDA = [&](int kt) {
        int gr = m0 + rA; if (gr >= n_nodes) gr = n_nodes - 1;
        const float4* p = (const float4*)(x + (long long)gr * D + kt * 32 + hA * 16 + sub * 8);
        rav[0] = p[0]; rav[1] = p[1];
    };
    auto STA = [&](int buf) {
        unsigned* base = Af + buf * NACH_WORDS + ((rA >> 4) * 2 + hA) * AW + gA * 16 + rsA;
#pragma unroll
        for (int ii = 0; ii < 2; ii++) {
            int i = sub * 2 + ii;
            unsigned* q = base + (i & 1) * 8 + (i >> 1) * 2;
            q[0] = f2h2(rav[ii].x, rav[ii].y);
            q[4] = f2h2(rav[ii].z, rav[ii].w);
        }
    };
    const __half* Brow = g_W1h + (long long)(tid >> 1) * 512 + n0 + (tid & 1) * 16;
    auto LDW = [&](int kt) { ldBh2(Brow + kt * 32, rwv); };
    auto STW = [&](int buf) { stBh2(Bf + buf * BCH_WORDS, tid, rwv); };

    float acc[4][4][4];
#pragma unroll
    for (int a = 0; a < 4; a++)
#pragma unroll
        for (int b = 0; b < 4; b++)
#pragma unroll
            for (int c = 0; c < 4; c++) acc[a][b][c] = 0.f;

    LDA(0); LDW(0); STA(0); STW(0);
    __syncthreads();

    for (int kt = 0; kt < 8; ++kt) {
        const int cur = kt & 1;
        if (kt < 7) { LDA(kt + 1); LDW(kt + 1); }
        const unsigned* Ac = Af + cur * NACH_WORDS;
        const unsigned* Bc = Bf + cur * BCH_WORDS;
#pragma unroll
        for (int h = 0; h < 2; ++h) {
            uint4 af[4]; uint2 bf[4];
#pragma unroll
            for (int mi = 0; mi < 4; ++mi)
                af[mi] = *(const uint4*)(Ac + ((wm * 4 + mi) * 2 + h) * AW + lane * 4);
#pragma unroll
            for (int ni = 0; ni < 4; ++ni)
                bf[ni] = *(const uint2*)(Bc + ((wn * 4 + ni) * 2 + h) * BW + lane * 2);
#pragma unroll
            for (int mi = 0; mi < 4; ++mi)
#pragma unroll
                for (int ni = 0; ni < 4; ++ni)
                    mma16(acc[mi][ni], (const unsigned*)&af[mi], (const unsigned*)&bf[ni]);
        }
        if (kt < 7) { STA(cur ^ 1); STW(cur ^ 1); }
        __syncthreads();
    }

#pragma unroll
    for (int mi = 0; mi < 4; ++mi) {
        int r0 = m0 + wm * 64 + mi * 16 + g;
        int r1 = r0 + 8;
#pragma unroll
        for (int ni = 0; ni < 4; ++ni) {
            int c = n0 + wn * 32 + ni * 8 + tg * 2;
            if (r0 < n_nodes)
                *(float2*)(g_PQ + (long long)r0 * 512 + c) = make_float2(acc[mi][ni][0], acc[mi][ni][1]);
            if (r1 < n_nodes)
                *(float2*)(g_PQ + (long long)r1 * 512 + c) = make_float2(acc[mi][ni][2], acc[mi][ni][3]);
        }
    }
}

// ---------------------------------------------------------------------------
// Kernel 2: index dtype detection (JAX x64-off downgrades int64 -> int32).
// ---------------------------------------------------------------------------
__global__ void detect_idx64(const int* __restrict__ p, int E) {
    __shared__ int ok;
    if (threadIdx.x == 0) ok = 1;
    __syncthreads();
    int n = E < 1024 ? E : 1024;
    int bad = 0;
    for (int i = threadIdx.x; i < n; i += blockDim.x)
        if (p[2 * i + 1] != 0) bad = 1;
    if (bad) atomicAnd(&ok, 0);
    __syncthreads();
    if (threadIdx.x == 0) g_is64 = ok;
}

// ---------------------------------------------------------------------------
// Kernel 3: 128 edges/CTA, 512 threads. Gather H1 = relu(P[src]+Q[dst]+b1)
// into fp16 fragment layout; one N=256 MMA pass (warp 64x32); fused epilogue.
// ---------------------------------------------------------------------------
__global__ __launch_bounds__(512) void edge_mlp(const void* __restrict__ srcv,
                                                const void* __restrict__ dstv,
                                                const float* __restrict__ b1,
                                                const float* __restrict__ b2,
                                                const float* __restrict__ W3,
                                                const float* __restrict__ b3,
                                                float* __restrict__ out, int E) {
    extern __shared__ unsigned sm[];
    unsigned* Af = sm;                        // [EA_WORDS]
    unsigned* Bf = sm + EA_WORDS;             // [2][BCH_WORDS]
    float* b2s   = (float*)(Bf + 2 * BCH_WORDS);  // 256
    float* w3s   = b2s + 256;                     // 256
    float* b1s   = w3s + 256;                     // 256
    float* score = b1s + 256;                     // 128

    const int tid = threadIdx.x, lane = tid & 31, warp = tid >> 5;
    const int wm = warp >> 3, wn = warp & 7;
    const int g = lane >> 2, tg = lane & 3;
    const int e0 = blockIdx.x * 128;
    const int is64 = g_is64;

    if (tid < 256) {
        b2s[tid] = b2[tid];
        w3s[tid] = W3[tid];
        b1s[tid] = b1[tid];
    }
    if (tid < 128) score[tid] = b3[0];
    __syncthreads();

    uint4 rwv[2];
    const __half* Brow = g_W2h + (long long)(tid >> 1) * 256 + (tid & 1) * 16;
    auto LDW = [&](int kt) { ldBh2(Brow + kt * 32, rwv); };
    auto STW = [&](int buf) { stBh2(Bf + buf * BCH_WORDS, tid, rwv); };

    LDW(0);  // overlap W2 chunk-0 loads with the gather

    // ---- gather + layer 1, written directly in fp16 fragment layout ----
    // thread: row r = tid>>2 (4 threads per row), l4 = tid&3
    {
        const int r = tid >> 2, l4 = tid & 3;
        int e = e0 + r;
        if (e >= E) e = 0;   // garbage rows computed, never stored
        long long s, d;
        if (is64) { s = ((const long long*)srcv)[e]; d = ((const long long*)dstv)[e]; }
        else      { s = ((const int*)srcv)[e];       d = ((const int*)dstv)[e]; }
        const float* Pr = g_PQ + s * 512;
        const float* Qr = g_PQ + d * 512 + 256;
        const int Mi = r >> 4, gg = (r & 15) & 7, rs = (r & 15) >> 3;
        unsigned* blk = Af + Mi * 16 * AW + gg * 16 + rs;
#pragma unroll
        for (int i = 0; i < 16; i++) {
            int c4 = i * 4 + l4;      // float4 index, 0..63
            float4 p  = *(const float4*)(Pr + c4 * 4);
            float4 q  = *(const float4*)(Qr + c4 * 4);
            float4 bb = *(const float4*)(b1s + c4 * 4);
            float h0 = fmaxf(p.x + q.x + bb.x, 0.f);
            float h1 = fmaxf(p.y + q.y + bb.y, 0.f);
            float h2 = fmaxf(p.z + q.z + bb.z, 0.f);
            float h3 = fmaxf(p.w + q.w + bb.w, 0.f);
            const int Kk = c4 >> 2, ii = c4 & 3;
            unsigned* qp = blk + Kk * AW + (ii & 1) * 8 + (ii >> 1) * 2;
            qp[0] = f2h2(h0, h1);
            qp[4] = f2h2(h2, h3);
        }
    }
    STW(0);
    __syncthreads();

    float acc[4][4][4];
#pragma unroll
    for (int a = 0; a < 4; a++)
#pragma unroll
        for (int b = 0; b < 4; b++)
#pragma unroll
            for (int c = 0; c < 4; c++) acc[a][b][c] = 0.f;

    for (int kt = 0; kt < 8; ++kt) {
        const int cur = kt & 1;
        if (kt < 7) LDW(kt + 1);
        const unsigned* Bc = Bf + cur * BCH_WORDS;
#pragma unroll
        for (int h = 0; h < 2; ++h) {
            const int Kkg = kt * 2 + h;
            uint4 af[4]; uint2 bf[4];
#pragma unroll
            for (int mi = 0; mi < 4; ++mi)
                af[mi] = *(const uint4*)(Af + ((wm * 4 + mi) * 16 + Kkg) * AW + lane * 4);
#pragma unroll
            for (int ni = 0; ni < 4; ++ni)
                bf[ni] = *(const uint2*)(Bc + ((wn * 4 + ni) * 2 + h) * BW + lane * 2);
#pragma unroll
            for (int mi = 0; mi < 4; ++mi)
#pragma unroll
                for (int ni = 0; ni < 4; ++ni)
                    mma16(acc[mi][ni], (const unsigned*)&af[mi], (const unsigned*)&bf[ni]);
        }
        if (kt < 7) STW(cur ^ 1);
        __syncthreads();
    }

    // ---- fused layer-2 bias/relu + layer-3 dot reduction ----
#pragma unroll
    for (int mi = 0; mi < 4; ++mi) {
        float rs0 = 0.f, rs1 = 0.f;
#pragma unroll
        for (int ni = 0; ni < 4; ++ni) {
            int n = wn * 32 + ni * 8 + tg * 2;
            float w0 = w3s[n], w1 = w3s[n + 1];
            float c0 = b2s[n], c1 = b2s[n + 1];
            rs0 += fmaxf(acc[mi][ni][0] + c0, 0.f) * w0 + fmaxf(acc[mi][ni][1] + c1, 0.f) * w1;
            rs1 += fmaxf(acc[mi][ni][2] + c0, 0.f) * w0 + fmaxf(acc[mi][ni][3] + c1, 0.f) * w1;
        }
        rs0 += __shfl_xor_sync(0xffffffffu, rs0, 1);
        rs0 += __shfl_xor_sync(0xffffffffu, rs0, 2);
        rs1 += __shfl_xor_sync(0xffffffffu, rs1, 1);
        rs1 += __shfl_xor_sync(0xffffffffu, rs1, 2);
        if (tg == 0) {
            atomicAdd(&score[wm * 64 + mi * 16 + g], rs0);
            atomicAdd(&score[wm * 64 + mi * 16 + g + 8], rs1);
        }
    }
    __syncthreads();

    if (tid < 128) {
        int e = e0 + tid;
        if (e < E) out[e] = score[tid];
    }
}

// ---------------------------------------------------------------------------
// Launch
// ---------------------------------------------------------------------------
extern "C" void kernel_launch(void* const* d_in, const int* in_sizes, int n_in,
                              void* d_out, int out_size) {
    const float* x  = (const float*)d_in[0];
    const void*  sv = d_in[1];
    const void*  dv = d_in[2];
    const float* W1 = (const float*)d_in[3];
    const float* b1 = (const float*)d_in[4];
    const float* W2 = (const float*)d_in[5];
    const float* b2 = (const float*)d_in[6];
    const float* W3 = (const float*)d_in[7];
    const float* b3 = (const float*)d_in[8];
    float* out = (float*)d_out;

    const int n_nodes = in_sizes[0] / D;
    const int E       = in_sizes[1];

    const int SM_NODE = (2 * NACH_WORDS + 2 * BCH_WORDS) * 4;   // 50688 B
    const int SM_EDGE = (EA_WORDS + 2 * BCH_WORDS + 896) * 4;   // 104960 B
    cudaFuncSetAttribute(node_gemm, cudaFuncAttributeMaxDynamicSharedMemorySize, SM_NODE);
    cudaFuncSetAttribute(edge_mlp,  cudaFuncAttributeMaxDynamicSharedMemorySize, SM_EDGE);

    convert_weights<<<192, 256>>>(W1, W2);

    dim3 g1((n_nodes + 127) / 128, 2);
    node_gemm<<<g1, 512, SM_NODE>>>(x, n_nodes);

    detect_idx64<<<1, 256>>>((const int*)sv, E);

    int g2 = (E + 127) / 128;
    edge_mlp<<<g2, 512, SM_EDGE>>>(sv, dv, b1, b2, W3, b3, out, E);
}